// round 6
// baseline (speedup 1.0000x reference)
#include <cuda_runtime.h>
#include <cuda_fp16.h>

#define FD 16

// ---- fp8 channels-last plane pool: texel = 16 e4m3 bytes, value scale x256 ----------
#define T_XTYT0 0
#define T_XY0   4096
#define T_XTYT1 20480
#define T_XY1   36864
#define T_XTYT2 102400
#define T_XY2   167936
#define T_TOTAL 430080

__device__ __align__(16) unsigned char g_planes[(size_t)T_TOTAL * 16];
__device__ __align__(16) __half g_w1t[32 * 48];  // [j][i], pre-scaled by 1/256
__device__ float g_b1[32];
__device__ float g_w2[64];   // row-major (32,2)
__device__ float g_b2[2];

__device__ __forceinline__ unsigned short pack_e4m3(float hi, float lo) {
    unsigned short r;
    asm("cvt.rn.satfinite.e4m3x2.f32 %0, %1, %2;" : "=h"(r) : "f"(hi), "f"(lo));
    return r;
}

// All 6 planes: (P, C, H, W) float -> [texel][c] e4m3 (x256).  One thread per texel.
__global__ void prep_planes(const float* __restrict__ xtyt0, const float* __restrict__ xy0,
                            const float* __restrict__ xtyt1, const float* __restrict__ xy1,
                            const float* __restrict__ xtyt2, const float* __restrict__ xy2) {
    int t = blockIdx.x * blockDim.x + threadIdx.x;
    if (t >= T_TOTAL) return;
    const float* src; int H, W, loc;
    if      (t < T_XY0)   { src = xtyt0; H = 16;  W = 128; loc = t; }
    else if (t < T_XTYT1) { src = xy0;   H = 128; W = 128; loc = t - T_XY0; }
    else if (t < T_XY1)   { src = xtyt1; H = 32;  W = 256; loc = t - T_XTYT1; }
    else if (t < T_XTYT2) { src = xy1;   H = 256; W = 256; loc = t - T_XY1; }
    else if (t < T_XY2)   { src = xtyt2; H = 64;  W = 512; loc = t - T_XTYT2; }
    else                  { src = xy2;   H = 512; W = 512; loc = t - T_XY2; }
    int w = loc % W; int rest = loc / W; int h = rest % H; int p = rest / H;
    size_t HW = (size_t)H * W;
    const float* s = src + ((size_t)p * FD * H + h) * W + w;
    float f[16];
#pragma unroll
    for (int c = 0; c < 16; c++) f[c] = s[c * HW] * 256.0f;
    unsigned o[4];
#pragma unroll
    for (int q = 0; q < 4; q++) {
        unsigned short lo = pack_e4m3(f[4 * q + 1], f[4 * q + 0]);
        unsigned short hi = pack_e4m3(f[4 * q + 3], f[4 * q + 2]);
        o[q] = (unsigned)lo | ((unsigned)hi << 16);
    }
    *reinterpret_cast<uint4*>(g_planes + (size_t)t * 16) = make_uint4(o[0], o[1], o[2], o[3]);
}

__global__ void prep_weights(const float* __restrict__ w1, const float* __restrict__ b1,
                             const float* __restrict__ w2, const float* __restrict__ b2) {
    int t = threadIdx.x;
    for (int idx = t; idx < 32 * 48; idx += blockDim.x) {
        int j = idx / 48, i = idx % 48;
        g_w1t[idx] = __float2half_rn(w1[i * 32 + j] * (1.0f / 256.0f));  // fold fp8 scale
    }
    if (t < 32) g_b1[t] = b1[t];
    if (t < 64) g_w2[t] = w2[t];
    if (t < 2)  g_b2[t] = b2[t];
}

// ---------------- main kernel -------------------------------------------------------

struct Ax { int s; float f; };

__device__ __forceinline__ Ax conv(float g, int R) {
    float x = (g + 1.0f) * 0.5f * (float)(R - 1);
    int s = (int)floorf(x);
    s = min(s, R - 2);
    s = max(s, 0);
    Ax a; a.s = s; a.f = x - (float)s; return a;
}

__device__ __forceinline__ __half2 cvt8(unsigned short v) {
    unsigned r;
    asm("cvt.rn.f16x2.e4m3x2 %0, %1;" : "=r"(r) : "h"(v));
    return *reinterpret_cast<__half2*>(&r);
}

__device__ __forceinline__ void acc_texel(uint4 d, __half2 w, __half2* acc) {
    unsigned v[4] = { d.x, d.y, d.z, d.w };
#pragma unroll
    for (int q = 0; q < 4; q++) {
        __half2 h0 = cvt8((unsigned short)(v[q] & 0xFFFFu));
        __half2 h1 = cvt8((unsigned short)(v[q] >> 16));
        acc[2 * q]     = __hfma2(h0, w, acc[2 * q]);
        acc[2 * q + 1] = __hfma2(h1, w, acc[2 * q + 1]);
    }
}

// Lane-pair cooperative sample: lane l loads the x-side (X.s + l) texel for both rows.
__device__ __forceinline__ void samp(const unsigned char* __restrict__ plane, int W,
                                     Ax X, Ax Y, float wl, int l, __half2* acc) {
    const unsigned char* p0 = plane + ((size_t)(Y.s * W + X.s + l) << 4);
    uint4 d0 = __ldg(reinterpret_cast<const uint4*>(p0));
    uint4 d1 = __ldg(reinterpret_cast<const uint4*>(p0 + (size_t)W * 16));
    acc_texel(d0, __float2half2_rn(wl * (1.0f - Y.f)), acc);
    acc_texel(d1, __float2half2_rn(wl * Y.f), acc);
}

template<int RX, int RT>
__device__ __forceinline__ void level(const unsigned char* __restrict__ xtyt,
                                      const unsigned char* __restrict__ xy,
                                      float cx, float cy, float ct,
                                      int l, __half2* acc) {
    Ax u = conv(cx, RX);
    Ax v = conv(cy, RX);
    Ax w = conv(ct, RT);
    float fu = l ? u.f : 1.0f - u.f;
    float fv = l ? v.f : 1.0f - v.f;
    samp(xtyt,                      RX, u, w, fu, l, acc);   // f_xt
    samp(xtyt + (size_t)RT*RX*16,   RX, v, w, fv, l, acc);   // f_yt
    samp(xy,                        RX, u, v, fu, l, acc);   // f_xy
}

__global__ void __launch_bounds__(256)
triplane_kernel(const float* __restrict__ coords, float2* __restrict__ out, int N) {
    __shared__ __align__(16) float scoord[256 * 3];
    __shared__ __align__(16) __half2 sw1t[32 * 24];
    __shared__ float sb1[32], sw2[64], sb2[2];
    {
        const __half2* src = reinterpret_cast<const __half2*>(g_w1t);
        for (int t = threadIdx.x; t < 32 * 24; t += 256) sw1t[t] = src[t];
        if (threadIdx.x < 32) sb1[threadIdx.x] = g_b1[threadIdx.x];
        if (threadIdx.x < 64) sw2[threadIdx.x] = g_w2[threadIdx.x];
        if (threadIdx.x < 2)  sb2[threadIdx.x] = g_b2[threadIdx.x];
    }
    int base = blockIdx.x * 256;
    {
        int lim = min(3 * N - 3 * base, 768);
        const float* cp = coords + 3 * base;
        for (int t = threadIdx.x; t < 768; t += 256)
            scoord[t] = cp[min(t, lim - 1)];
    }
    __syncthreads();

    int l = threadIdx.x & 1;   // x-side lane within the pair

#pragma unroll 1
    for (int r = 0; r < 2; r++) {
        int row = r * 128 + (threadIdx.x >> 1);
        int rc  = min(row, N - 1 - base);
        float cx = scoord[3 * rc + 0];
        float cy = scoord[3 * rc + 1];
        float ct = scoord[3 * rc + 2];

        __half2 acc[24];
#pragma unroll
        for (int k = 0; k < 24; k++) acc[k] = __float2half2_rn(0.0f);

        level<128, 16>(g_planes + (size_t)T_XTYT0 * 16, g_planes + (size_t)T_XY0 * 16,
                       cx, cy, ct, l, acc + 0);
        level<256, 32>(g_planes + (size_t)T_XTYT1 * 16, g_planes + (size_t)T_XY1 * 16,
                       cx, cy, ct, l, acc + 8);
        level<512, 64>(g_planes + (size_t)T_XTYT2 * 16, g_planes + (size_t)T_XY2 * 16,
                       cx, cy, ct, l, acc + 16);

        // combine x0/x1 partial sums across the lane pair -> full features in both lanes
#pragma unroll
        for (int k = 0; k < 24; k++) {
            unsigned o = __shfl_xor_sync(0xFFFFFFFFu,
                                         *reinterpret_cast<unsigned*>(&acc[k]), 1);
            acc[k] = __hadd2(acc[k], *reinterpret_cast<__half2*>(&o));
        }

        // fused MLP: lane l handles hidden units j = 16*l .. 16*l+15
        float z0 = 0.0f, z1 = 0.0f;
#pragma unroll 4
        for (int jj = 0; jj < 16; jj++) {
            int j = l * 16 + jj;
            const __half2* wr = sw1t + j * 24;
            __half2 sa = __hmul2(acc[0], wr[0]);
            __half2 sb = __hmul2(acc[1], wr[1]);
#pragma unroll
            for (int k = 2; k < 24; k += 2) {
                sa = __hfma2(acc[k],     wr[k],     sa);
                sb = __hfma2(acc[k + 1], wr[k + 1], sb);
            }
            sa = __hadd2(sa, sb);
            float hj = __low2float(sa) + __high2float(sa) + sb1[j];
            hj = hj > 0.0f ? hj : 0.01f * hj;
            z0 = fmaf(hj, sw2[2 * j + 0], z0);
            z1 = fmaf(hj, sw2[2 * j + 1], z1);
        }
        z0 += __shfl_xor_sync(0xFFFFFFFFu, z0, 1);
        z1 += __shfl_xor_sync(0xFFFFFFFFu, z1, 1);

        if (l == 0 && base + row < N) {
            float2 o;
            o.x = 1.0f / (1.0f + __expf(-(z0 + sb2[0])));
            o.y = 1.0f / (1.0f + __expf(-(z1 + sb2[1])));
            out[base + row] = o;
        }
    }
}

// ---------------- launch ------------------------------------------------------------
extern "C" void kernel_launch(void* const* d_in, const int* in_sizes, int n_in,
                              void* d_out, int out_size) {
    const float* coords = (const float*)d_in[0];
    const float* xtyt0  = (const float*)d_in[1];
    const float* xy0    = (const float*)d_in[2];
    const float* xtyt1  = (const float*)d_in[3];
    const float* xy1    = (const float*)d_in[4];
    const float* xtyt2  = (const float*)d_in[5];
    const float* xy2    = (const float*)d_in[6];
    const float* w1     = (const float*)d_in[7];
    const float* b1     = (const float*)d_in[8];
    const float* w2     = (const float*)d_in[9];
    const float* b2     = (const float*)d_in[10];
    int N = in_sizes[0] / 3;

    prep_planes<<<(T_TOTAL + 255) / 256, 256>>>(xtyt0, xy0, xtyt1, xy1, xtyt2, xy2);
    prep_weights<<<1, 256>>>(w1, b1, w2, b2);

    int blocks = (N + 255) / 256;
    triplane_kernel<<<blocks, 256>>>(coords, (float2*)d_out, N);
}